// round 16
// baseline (speedup 1.0000x reference)
#include <cuda_runtime.h>
#include <cuda_bf16.h>
#include <cstdint>
#include <math.h>

#define PB 16
#define PP 64
#define PF 128
#define PH 8
#define PDM 512
#define PBP 1024

typedef unsigned long long u64;

// ================= helpers =================
__device__ __forceinline__ uint32_t smem_to_u32(const void* p) {
    uint32_t a;
    asm("{ .reg .u64 t; cvta.to.shared.u64 t, %1; cvt.u32.u64 %0, t; }" : "=r"(a) : "l"(p));
    return a;
}

#define SW128(o) ((o) ^ (((o) >> 3) & 0x70))

#define LDMX4(r, a) \
    asm volatile("ldmatrix.sync.aligned.m8n8.x4.shared.b16 {%0,%1,%2,%3}, [%4];" \
        : "=r"((r)[0]), "=r"((r)[1]), "=r"((r)[2]), "=r"((r)[3]) : "r"(a))

#define LDMX4T(r, a) \
    asm volatile("ldmatrix.sync.aligned.m8n8.x4.trans.shared.b16 {%0,%1,%2,%3}, [%4];" \
        : "=r"((r)[0]), "=r"((r)[1]), "=r"((r)[2]), "=r"((r)[3]) : "r"(a))

#define MMA_BF16(c, a, b) \
    asm volatile("mma.sync.aligned.m16n8k16.row.col.f32.bf16.bf16.f32 " \
        "{%0,%1,%2,%3}, {%4,%5,%6,%7}, {%8,%9}, {%0,%1,%2,%3};" \
        : "+f"((c)[0]), "+f"((c)[1]), "+f"((c)[2]), "+f"((c)[3]) \
        : "r"((a)[0]), "r"((a)[1]), "r"((a)[2]), "r"((a)[3]), "r"((b)[0]), "r"((b)[1]))

// ================= scratch =================
__device__ float g_sb[PB * PH * PP * PP];
__device__ __nv_bfloat16 g_pe_hi[PBP * PDM], g_pe_lo[PBP * PDM];
__device__ __nv_bfloat16 g_qh[PBP * PDM],   g_ql[PBP * PDM];
__device__ __nv_bfloat16 g_kbh[PBP * PDM],  g_kbl[PBP * PDM];
__device__ __nv_bfloat16 g_vbh[PBP * PDM],  g_vbl[PBP * PDM];
__device__ __nv_bfloat16 g_qkh[PBP * PH * PF], g_qkl[PBP * PH * PF];
__device__ __nv_bfloat16 g_ath[PB * PH * PP * PP], g_atl[PB * PH * PP * PP];
__device__ __nv_bfloat16 g_arh[PBP * PH * PF], g_arl[PBP * PH * PF];
__device__ __nv_bfloat16 g_cb_hi[PBP * PDM], g_cb_lo[PBP * PDM];
__device__ __nv_bfloat16 g_wt_hi[4 * 512 * 512], g_wt_lo[4 * 512 * 512];
__device__ __nv_bfloat16 g_wkf_hi[PF * PDM], g_wkf_lo[PF * PDM];
__device__ __nv_bfloat16 g_wvfh[PF * PDM],  g_wvfl[PF * PDM];

__device__ __forceinline__ void bsplit(float x, __nv_bfloat16& h, __nv_bfloat16& l)
{
    h = __float2bfloat16_rn(x);
    l = __float2bfloat16_rn(x - __bfloat162float(h));
}
__device__ __forceinline__ void bsplit2(float a, float b, uint32_t& h2, uint32_t& l2)
{
    asm("cvt.rn.bf16x2.f32 %0, %1, %2;" : "=r"(h2) : "f"(b), "f"(a));
    float af = __uint_as_float(h2 << 16);
    float bf = __uint_as_float(h2 & 0xFFFF0000u);
    float ar = a - af, br = b - bf;
    asm("cvt.rn.bf16x2.f32 %0, %1, %2;" : "=r"(l2) : "f"(br), "f"(ar));
}

// ================= prep: pe split | W transpose+split | Wkf/Wvf split =================
__global__ void __launch_bounds__(256) prep_kernel(const float* __restrict__ pe,
                                                   const float* __restrict__ Wq,
                                                   const float* __restrict__ Wk,
                                                   const float* __restrict__ Wv,
                                                   const float* __restrict__ Wo)
{
    const int bx = blockIdx.x, tid = threadIdx.x;

    if (bx < 512) {
        int idx = bx * 256 + tid;
        float4 v = *(const float4*)(pe + (size_t)idx * 4);
        uint2 h2, l2;
        bsplit2(v.x, v.y, h2.x, l2.x);
        bsplit2(v.z, v.w, h2.y, l2.y);
        *(uint2*)(g_pe_hi + (size_t)idx * 4) = h2;
        *(uint2*)(g_pe_lo + (size_t)idx * 4) = l2;
    } else if (bx < 1536) {
        __shared__ float tile[32 * 33];
        const int wb = bx - 512;
        const int z = wb >> 8, rem = wb & 255;
        const int n0 = (rem & 15) * 32, k0 = (rem >> 4) * 32;
        const float* W = (z == 0) ? Wq : (z == 1) ? Wk : (z == 2) ? Wv : Wo;
        const int tx = tid & 31, ty = tid >> 5;
#pragma unroll
        for (int j = 0; j < 4; j++)
            tile[(ty + j * 8) * 33 + tx] = W[(size_t)(k0 + ty + j * 8) * 512 + n0 + tx];
        __syncthreads();
#pragma unroll
        for (int j = 0; j < 4; j++) {
            float v = tile[tx * 33 + ty + j * 8];
            __nv_bfloat16 h, l; bsplit(v, h, l);
            size_t o = (size_t)z * 262144 + (size_t)(n0 + ty + j * 8) * 512 + k0 + tx;
            g_wt_hi[o] = h; g_wt_lo[o] = l;
        }
    } else {
        const int which = (bx - 1536) >> 6;
        const int idx = ((bx - 1536) & 63) * 256 + tid;
        const float* src = (which == 0) ? Wk : Wv;
        float4 v = *(const float4*)(src + (size_t)512 * 512 + (size_t)idx * 4);
        uint2 h2, l2;
        bsplit2(v.x, v.y, h2.x, l2.x);
        bsplit2(v.z, v.w, h2.y, l2.y);
        __nv_bfloat16* dh = (which == 0) ? g_wkf_hi : g_wvfh;
        __nv_bfloat16* dl = (which == 0) ? g_wkf_lo : g_wvfl;
        *(uint2*)(dh + (size_t)idx * 4) = h2;
        *(uint2*)(dl + (size_t)idx * 4) = l2;
    }
}

// ================= 64x64 warp-MMA tile (128 threads) — used by qs =================
__device__ __forceinline__ void mma_gemm(const __nv_bfloat16* __restrict__ Ahi,
                                         const __nv_bfloat16* __restrict__ Alo,
                                         int m0, int koffA,
                                         const __nv_bfloat16* __restrict__ Bhi,
                                         const __nv_bfloat16* __restrict__ Blo,
                                         int n0, int koffB, int nch,
                                         float* Cf, __nv_bfloat16* Ch, __nv_bfloat16* Cl, int ldc)
{
    __shared__ __nv_bfloat16 sAh[4096], sAl[4096], sBh[4096], sBl[4096];
    const int tid = threadIdx.x, lane = tid & 31, wid = tid >> 5;
    const int wm = (wid & 1) * 32, wn = (wid >> 1) * 32;
    const int lr = tid >> 1, lh = tid & 1;

    const uint32_t bAh = smem_to_u32(sAh), bAl = smem_to_u32(sAl);
    const uint32_t bBh = smem_to_u32(sBh), bBl = smem_to_u32(sBl);

    const uint32_t rowA = wm + (lane & 15);
    const uint32_t kbA  = (lane >> 4) * 16;
    const uint32_t rowB = wn + (lane & 7) + ((lane >> 4) << 3);
    const uint32_t kbB  = ((lane >> 3) & 1) * 16;

    uint4 pAh[4], pAl[4], pBh[4], pBl[4];

    auto load_chunk = [&](int ch) {
        const size_t aoff = (size_t)(m0 + lr) * 512 + koffA + ch * 64 + lh * 32;
        const size_t boff = (size_t)(n0 + lr) * 512 + koffB + ch * 64 + lh * 32;
#pragma unroll
        for (int j = 0; j < 4; j++) {
            pAh[j] = ((const uint4*)(Ahi + aoff))[j];
            pAl[j] = ((const uint4*)(Alo + aoff))[j];
            pBh[j] = ((const uint4*)(Bhi + boff))[j];
            pBl[j] = ((const uint4*)(Blo + boff))[j];
        }
    };
    auto store_chunk = [&]() {
#pragma unroll
        for (int j = 0; j < 4; j++) {
            uint32_t o = SW128((uint32_t)(lr * 128 + lh * 64 + j * 16));
            *(uint4*)((char*)sAh + o) = pAh[j];
            *(uint4*)((char*)sAl + o) = pAl[j];
            *(uint4*)((char*)sBh + o) = pBh[j];
            *(uint4*)((char*)sBl + o) = pBl[j];
        }
    };

    float c[2][4][4] = {};

    load_chunk(0);
    store_chunk();
    __syncthreads();

    for (int ch = 0; ch < nch; ch++) {
        if (ch + 1 < nch) load_chunk(ch + 1);

#pragma unroll
        for (int ks = 0; ks < 4; ks++) {
            const uint32_t kA = ks * 32 + kbA;
            const uint32_t kB = ks * 32 + kbB;
            const uint32_t oA0 = SW128(rowA * 128 + kA);
            const uint32_t oA1 = SW128((rowA + 16) * 128 + kA);
            const uint32_t oB0 = SW128(rowB * 128 + kB);
            const uint32_t oB1 = SW128((rowB + 16) * 128 + kB);

            uint32_t ah0[4], ah1[4], al0[4], al1[4];
            LDMX4(ah0, bAh + oA0); LDMX4(ah1, bAh + oA1);
            LDMX4(al0, bAl + oA0); LDMX4(al1, bAl + oA1);
            uint32_t bh0[4], bh1[4], bl0[4], bl1[4];
            LDMX4(bh0, bBh + oB0); LDMX4(bh1, bBh + oB1);
            LDMX4(bl0, bBl + oB0); LDMX4(bl1, bBl + oB1);

            uint32_t* Ah[2] = { ah0, ah1 };
            uint32_t* Al[2] = { al0, al1 };
            uint32_t* Bh[4] = { bh0, bh0 + 2, bh1, bh1 + 2 };
            uint32_t* Bl[4] = { bl0, bl0 + 2, bl1, bl1 + 2 };
#pragma unroll
            for (int mt = 0; mt < 2; mt++) {
#pragma unroll
                for (int j = 0; j < 4; j++) {
                    MMA_BF16(c[mt][j], Ah[mt], Bh[j]);
                    MMA_BF16(c[mt][j], Ah[mt], Bl[j]);
                    MMA_BF16(c[mt][j], Al[mt], Bh[j]);
                }
            }
        }
        if (ch + 1 < nch) {
            __syncthreads();
            store_chunk();
            __syncthreads();
        }
    }

    const int g = lane >> 2, cc = (lane & 3) * 2;
#pragma unroll
    for (int mt = 0; mt < 2; mt++)
#pragma unroll
        for (int j = 0; j < 4; j++) {
            int row = wm + mt * 16 + g;
            int col = wn + j * 8 + cc;
            if (Cf) {
                *(float2*)(Cf + (size_t)row * ldc + col) = make_float2(c[mt][j][0], c[mt][j][1]);
                *(float2*)(Cf + (size_t)(row + 8) * ldc + col) = make_float2(c[mt][j][2], c[mt][j][3]);
            }
            if (Ch) {
                uint32_t h2, l2;
                bsplit2(c[mt][j][0], c[mt][j][1], h2, l2);
                *(uint32_t*)(Ch + (size_t)row * ldc + col) = h2;
                *(uint32_t*)(Cl + (size_t)row * ldc + col) = l2;
                bsplit2(c[mt][j][2], c[mt][j][3], h2, l2);
                *(uint32_t*)(Ch + (size_t)(row + 8) * ldc + col) = h2;
                *(uint32_t*)(Cl + (size_t)(row + 8) * ldc + col) = l2;
            }
        }
}

// ================= 128x64 warp-MMA tile (256 threads) — proj/final =================
__device__ __forceinline__ void mma_gemm128(const __nv_bfloat16* __restrict__ Ahi,
                                            const __nv_bfloat16* __restrict__ Alo,
                                            int m0,
                                            const __nv_bfloat16* __restrict__ Bhi,
                                            const __nv_bfloat16* __restrict__ Blo,
                                            int n0,
                                            float* Cf, __nv_bfloat16* Ch, __nv_bfloat16* Cl)
{
    __shared__ __nv_bfloat16 sAh[8192], sAl[8192], sBh[4096], sBl[4096];  // 48KB
    const int tid = threadIdx.x, lane = tid & 31, wid = tid >> 5;
    const int wm = (wid & 3) * 32, wn = (wid >> 2) * 32;
    const int alr = tid >> 1, alh = tid & 1;      // A: 128 rows, half (64B)
    const int blr = tid >> 2, blq = tid & 3;      // B: 64 rows, quarter (32B = 16 bf16)

    const uint32_t bAh = smem_to_u32(sAh), bAl = smem_to_u32(sAl);
    const uint32_t bBh = smem_to_u32(sBh), bBl = smem_to_u32(sBl);

    const uint32_t rowA = wm + (lane & 15);
    const uint32_t kbA  = (lane >> 4) * 16;
    const uint32_t rowB = wn + (lane & 7) + ((lane >> 4) << 3);
    const uint32_t kbB  = ((lane >> 3) & 1) * 16;

    uint4 pAh[4], pAl[4], pBh[2], pBl[2];

    auto load_chunk = [&](int ch) {
        const size_t aoff = (size_t)(m0 + alr) * 512 + ch * 64 + alh * 32;
        const size_t boff = (size_t)(n0 + blr) * 512 + ch * 64 + blq * 16;  // FIXED: quarter = 16 bf16
#pragma unroll
        for (int j = 0; j < 4; j++) {
            pAh[j] = ((const uint4*)(Ahi + aoff))[j];
            pAl[j] = ((const uint4*)(Alo + aoff))[j];
        }
#pragma unroll
        for (int j = 0; j < 2; j++) {
            pBh[j] = ((const uint4*)(Bhi + boff))[j];
            pBl[j] = ((const uint4*)(Blo + boff))[j];
        }
    };
    auto store_chunk = [&]() {
#pragma unroll
        for (int j = 0; j < 4; j++) {
            uint32_t o = SW128((uint32_t)(alr * 128 + alh * 64 + j * 16));
            *(uint4*)((char*)sAh + o) = pAh[j];
            *(uint4*)((char*)sAl + o) = pAl[j];
        }
#pragma unroll
        for (int j = 0; j < 2; j++) {
            uint32_t o = SW128((uint32_t)(blr * 128 + blq * 32 + j * 16));
            *(uint4*)((char*)sBh + o) = pBh[j];
            *(uint4*)((char*)sBl + o) = pBl[j];
        }
    };

    float c[2][4][4] = {};

    load_chunk(0);
    store_chunk();
    __syncthreads();

    for (int ch = 0; ch < 8; ch++) {
        if (ch + 1 < 8) load_chunk(ch + 1);

#pragma unroll
        for (int ks = 0; ks < 4; ks++) {
            const uint32_t kA = ks * 32 + kbA;
            const uint32_t kB = ks * 32 + kbB;
            const uint32_t oA0 = SW128(rowA * 128 + kA);
            const uint32_t oA1 = SW128((rowA + 16) * 128 + kA);
            const uint32_t oB0 = SW128(rowB * 128 + kB);
            const uint32_t oB1 = SW128((rowB + 16) * 128 + kB);

            uint32_t ah0[4], ah1[4], al0[4], al1[4];
            LDMX4(ah0, bAh + oA0); LDMX4(ah1, bAh + oA1);
            LDMX4(al0, bAl + oA0); LDMX4(al1, bAl + oA1);
            uint32_t bh0[4], bh1[4], bl0[4], bl1[4];
            LDMX4(bh0, bBh + oB0); LDMX4(bh1, bBh + oB1);
            LDMX4(bl0, bBl + oB0); LDMX4(bl1, bBl + oB1);

            uint32_t* Ah[2] = { ah0, ah1 };
            uint32_t* Al[2] = { al0, al1 };
            uint32_t* Bh[4] = { bh0, bh0 + 2, bh1, bh1 + 2 };
            uint32_t* Bl[4] = { bl0, bl0 + 2, bl1, bl1 + 2 };
#pragma unroll
            for (int mt = 0; mt < 2; mt++) {
#pragma unroll
                for (int j = 0; j < 4; j++) {
                    MMA_BF16(c[mt][j], Ah[mt], Bh[j]);
                    MMA_BF16(c[mt][j], Ah[mt], Bl[j]);
                    MMA_BF16(c[mt][j], Al[mt], Bh[j]);
                }
            }
        }
        if (ch + 1 < 8) {
            __syncthreads();
            store_chunk();
            __syncthreads();
        }
    }

    const int g = lane >> 2, cc = (lane & 3) * 2;
#pragma unroll
    for (int mt = 0; mt < 2; mt++)
#pragma unroll
        for (int j = 0; j < 4; j++) {
            int row = wm + mt * 16 + g;
            int col = wn + j * 8 + cc;
            if (Cf) {
                *(float2*)(Cf + (size_t)row * 512 + col) = make_float2(c[mt][j][0], c[mt][j][1]);
                *(float2*)(Cf + (size_t)(row + 8) * 512 + col) = make_float2(c[mt][j][2], c[mt][j][3]);
            }
            if (Ch) {
                uint32_t h2, l2;
                bsplit2(c[mt][j][0], c[mt][j][1], h2, l2);
                *(uint32_t*)(Ch + (size_t)row * 512 + col) = h2;
                *(uint32_t*)(Cl + (size_t)row * 512 + col) = l2;
                bsplit2(c[mt][j][2], c[mt][j][3], h2, l2);
                *(uint32_t*)(Ch + (size_t)(row + 8) * 512 + col) = h2;
                *(uint32_t*)(Cl + (size_t)(row + 8) * 512 + col) = l2;
            }
        }
}

// ================= proj: q, k_base, v_base bf16 hi/lo (128x64 tiles) =================
__global__ void __launch_bounds__(256) proj_mma_kernel()
{
    const int z = blockIdx.z;
    const int m0 = blockIdx.y * 128, n0 = blockIdx.x * 64;
    const size_t coff = (size_t)m0 * 512 + n0;
    __nv_bfloat16 *Ch, *Cl;
    if (z == 0)      { Ch = g_qh + coff;  Cl = g_ql + coff; }
    else if (z == 1) { Ch = g_kbh + coff; Cl = g_kbl + coff; }
    else             { Ch = g_vbh + coff; Cl = g_vbl + coff; }
    mma_gemm128(g_pe_hi, g_pe_lo, m0,
                g_wt_hi + (size_t)z * 262144, g_wt_lo + (size_t)z * 262144, n0,
                nullptr, Ch, Cl);
}

// ================= qs (64x64 path) =================
__global__ void __launch_bounds__(128) qs_kernel()
{
    if (blockIdx.x < 256) {
        const int h = blockIdx.x >> 5, r = blockIdx.x & 31;
        const int mt = r >> 1, nt = r & 1;
        const int m0 = mt * 64, n0 = nt * 64;
        const size_t coff = (size_t)m0 * 1024 + h * 128 + n0;
        mma_gemm(g_qh, g_ql, m0, h * 64,
                 g_wkf_hi, g_wkf_lo, n0, h * 64, 1,
                 nullptr, g_qkh + coff, g_qkl + coff, 1024);
    } else {
        const int sb = blockIdx.x - 256;
        const int b = sb >> 3, h = sb & 7;
        mma_gemm(g_qh, g_ql, b * 64, h * 64,
                 g_kbh, g_kbl, b * 64, h * 64, 1,
                 g_sb + (size_t)(b * 8 + h) * 4096, nullptr, nullptr, 64);
    }
}

// ================= attn: coalesced rf load; scores C=[p x h]; ar via x4.trans =================
__global__ void __launch_bounds__(256, 3) attn_mma_kernel(const float* __restrict__ rf)
{
    __shared__ __nv_bfloat16 rf_h[64 * 128], rf_l[64 * 128];
    __shared__ __nv_bfloat16 qk_h[8 * 128],  qk_l[8 * 128];
    __shared__ __nv_bfloat16 at_h[8 * 64],   at_l[8 * 64];
    __shared__ float s_s[8 * 68];

    const int bq = blockIdx.x;
    const int b = bq >> 6, q = bq & 63;
    const int tid = threadIdx.x, lane = tid & 31, w = tid >> 5;

    // ---- load + split rf: LINEAR coalesced (pidx = j*256+tid float4 units) ----
    {
        const float4* rfg = (const float4*)(rf + (size_t)bq * 8192);
        float4 raw[8];
#pragma unroll
        for (int j = 0; j < 8; j++) raw[j] = rfg[j * 256 + tid];
#pragma unroll
        for (int j = 0; j < 8; j++) {
            int pidx = j * 256 + tid;
            uint32_t h0, l0, h1, l1;
            bsplit2(raw[j].x, raw[j].y, h0, l0);
            bsplit2(raw[j].z, raw[j].w, h1, l1);
            int p = pidx >> 5, q4 = pidx & 31;
            uint32_t off = p * 256 + ((((uint32_t)q4 >> 1) ^ (p & 7)) << 4) + (q4 & 1) * 8;
            *(uint2*)((char*)rf_h + off) = make_uint2(h0, h1);
            *(uint2*)((char*)rf_l + off) = make_uint2(l0, l1);
        }
    }
    // ---- load qk (bf16 hi/lo, threads 0-127) ----
    if (tid < 128) {
        const int h = tid >> 4, c = tid & 15;
        const size_t o = (size_t)bq * 1024 + h * 128 + c * 8;
        uint4 hv = *(const uint4*)(g_qkh + o);
        uint4 lv = *(const uint4*)(g_qkl + o);
        int cs = c ^ h;
        *(uint4*)((char*)qk_h + h * 256 + cs * 16) = hv;
        *(uint4*)((char*)qk_l + h * 256 + cs * 16) = lv;
    }
    __syncthreads();

    const uint32_t bRfh = smem_to_u32(rf_h), bRfl = smem_to_u32(rf_l);

    // ---- scores_rel: warps 0-3, C = [16 p x 8 h], A = rf, B = qk ----
    if (w < 4) {
        const uint32_t bQh = smem_to_u32(qk_h), bQl = smem_to_u32(qk_l);
        const uint32_t prow = w * 16 + (lane & 15);
        const uint32_t akb = lane >> 4;
        const uint32_t brow = lane & 7;
        const uint32_t bcq = lane >> 3;

        float c0[4] = {};
#pragma unroll
        for (int ks32 = 0; ks32 < 4; ks32++) {
            uint32_t bh[4], bl[4];
            {
                uint32_t bc = ks32 * 4 + bcq;
                uint32_t boff = brow * 256 + ((bc ^ brow) << 4);
                LDMX4(bh, bQh + boff);
                LDMX4(bl, bQl + boff);
            }
#pragma unroll
            for (int half = 0; half < 2; half++) {
                uint32_t ac = (ks32 * 2 + half) * 2 + akb;
                uint32_t aoff = prow * 256 + ((ac ^ (prow & 7)) << 4);
                uint32_t ah[4], al[4];
                LDMX4(ah, bRfh + aoff);
                LDMX4(al, bRfl + aoff);
                MMA_BF16(c0, ah, bh + half * 2);
                MMA_BF16(c0, ah, bl + half * 2);
                MMA_BF16(c0, al, bh + half * 2);
            }
        }
        const int g = lane >> 2, hc = (lane & 3) * 2;
        const int p0 = w * 16 + g;
#pragma unroll
        for (int j = 0; j < 2; j++) {
            int h = hc + j;
            const float* sbr = g_sb + ((size_t)(b * 8 + h) * 64 + q) * 64;
            s_s[h * 68 + p0]     = 0.125f * (c0[j]     + sbr[p0]);
            s_s[h * 68 + p0 + 8] = 0.125f * (c0[2 + j] + sbr[p0 + 8]);
        }
    }
    __syncthreads();

    // ---- softmax: warp w -> head w ----
    {
        const int h = w, l = lane;
        float a0 = s_s[h * 68 + 2 * l], a1 = s_s[h * 68 + 2 * l + 1];
        float m = fmaxf(a0, a1);
#pragma unroll
        for (int off = 16; off; off >>= 1) m = fmaxf(m, __shfl_xor_sync(0xffffffffu, m, off));
        float e0 = __expf(a0 - m), e1 = __expf(a1 - m);
        float s = e0 + e1;
#pragma unroll
        for (int off = 16; off; off >>= 1) s += __shfl_xor_sync(0xffffffffu, s, off);
        float inv = 1.f / s;
        float p0 = e0 * inv, p1 = e1 * inv;
        uint32_t hh, ll;
        bsplit2(p0, p1, hh, ll);
        const size_t go = ((size_t)(b * 8 + h) * 64 + q) * 64 + 2 * l;
        *(uint32_t*)(g_ath + go) = hh;
        *(uint32_t*)(g_atl + go) = ll;
        uint32_t off8 = h * 128 + ((((uint32_t)l >> 2) ^ h) << 4) + (l & 3) * 4;
        *(uint32_t*)((char*)at_h + off8) = hh;
        *(uint32_t*)((char*)at_l + off8) = ll;
    }
    __syncthreads();

    // ---- ar: all 8 warps, warp w covers f [w*16, w*16+16); rf^T via x4.trans ----
    {
        const uint32_t bAth = smem_to_u32(at_h), bAtl = smem_to_u32(at_l);
        const int arow = lane & 7;
        const int akc = (lane >> 4) & 1;
        const int brow = lane & 15;
        const int f16i = w * 2 + (lane >> 4);

        float c[2][4] = {};
#pragma unroll
        for (int ks = 0; ks < 4; ks++) {
            uint32_t aoff = arow * 128 + (((ks * 2 + akc) ^ arow) << 4);
            uint32_t ah[4], al[4];
            LDMX4(ah, bAth + aoff); LDMX4(al, bAtl + aoff);
            const int p = ks * 16 + brow;
            uint32_t boff = p * 256 + ((f16i ^ (p & 7)) << 4);
            uint32_t bh[4], bl[4];
            LDMX4T(bh, bRfh + boff);
            LDMX4T(bl, bRfl + boff);
#pragma unroll
            for (int ft = 0; ft < 2; ft++) {
                MMA_BF16(c[ft], ah, bh + ft * 2);
                MMA_BF16(c[ft], ah, bl + ft * 2);
                MMA_BF16(c[ft], al, bh + ft * 2);
            }
        }
        const int h = lane >> 2, fc = (lane & 3) * 2;
        const size_t base = (size_t)bq * 1024 + h * 128 + w * 16;
#pragma unroll
        for (int ft = 0; ft < 2; ft++) {
            uint32_t hh, ll;
            bsplit2(c[ft][0], c[ft][1], hh, ll);
            *(uint32_t*)(g_arh + base + ft * 8 + fc) = hh;
            *(uint32_t*)(g_arl + base + ft * 8 + fc) = ll;
        }
    }
}

// ================= outmerge (tensor-core): cb = at@vb + ar@Wvf -> bf16 hi/lo =================
__global__ void __launch_bounds__(128) outmerge_mma_kernel()
{
    __shared__ __nv_bfloat16 sAh[4096], sAl[4096], sBh[4096], sBl[4096];
    const int bx = blockIdx.x;
    const int b = bx >> 3, h = bx & 7;
    const int tid = threadIdx.x, lane = tid & 31, w = tid >> 5;
    const int lr = tid >> 1, lh = tid & 1;

    const uint32_t aAh = smem_to_u32(sAh), aAl = smem_to_u32(sAl);
    const uint32_t aBh = smem_to_u32(sBh), aBl = smem_to_u32(sBl);

    float c[4][2][4] = {};

    for (int ch = 0; ch < 3; ch++) {
        const __nv_bfloat16 *Ah, *Al, *Bh, *Bl;
        size_t aoff, boff;
        if (ch == 0) {
            Ah = g_ath; Al = g_atl;
            aoff = ((size_t)(b * 8 + h) * 64 + lr) * 64 + lh * 32;
            Bh = g_vbh; Bl = g_vbl;
            boff = (size_t)(b * 64 + lr) * 512 + h * 64 + lh * 32;
        } else {
            const int fc = ch - 1;
            Ah = g_arh; Al = g_arl;
            aoff = (size_t)(b * 64 + lr) * 1024 + h * 128 + fc * 64 + lh * 32;
            Bh = g_wvfh; Bl = g_wvfl;
            boff = (size_t)(fc * 64 + lr) * 512 + h * 64 + lh * 32;
        }
        uint4 rAh[2], rAl[2], rBh[2], rBl[2];
        uint4 rAh2[2], rAl2[2], rBh2[2], rBl2[2];
#pragma unroll
        for (int j = 0; j < 2; j++) {
            rAh[j]  = ((const uint4*)(Ah + aoff))[j];
            rAl[j]  = ((const uint4*)(Al + aoff))[j];
            rBh[j]  = ((const uint4*)(Bh + boff))[j];
            rBl[j]  = ((const uint4*)(Bl + boff))[j];
            rAh2[j] = ((const uint4*)(Ah + aoff))[2 + j];
            rAl2[j] = ((const uint4*)(Al + aoff))[2 + j];
            rBh2[j] = ((const uint4*)(Bh + boff))[2 + j];
            rBl2[j] = ((const uint4*)(Bl + boff))[2 + j];
        }
        __syncthreads();
#pragma unroll
        for (int j = 0; j < 2; j++) {
            int c16a = (lh * 4 + j) ^ (lr & 7);
            int c16b = (lh * 4 + 2 + j) ^ (lr & 7);
            *(uint4*)((char*)sAh + lr * 128 + c16a * 16) = rAh[j];
            *(uint4*)((char*)sAl + lr * 128 + c16a * 16) = rAl[j];
            *(uint4*)((char*)sBh + lr * 128 + c16a * 16) = rBh[j];
            *(uint4*)((char*)sBl + lr * 128 + c16a * 16) = rBl[j];
            *(uint4*)((char*)sAh + lr * 128 + c16b * 16) = rAh2[j];
            *(uint4*)((char*)sAl + lr * 128 + c16b * 16) = rAl2[j];
            *(uint4*)((char*)sBh + lr * 128 + c16b * 16) = rBh2[j];
            *(uint4*)((char*)sBl + lr * 128 + c16b * 16) = rBl2[j];
        }
        __syncthreads();

#pragma unroll
        for (int ks = 0; ks < 4; ks++) {
            uint32_t ah[4][4], al[4][4];
#pragma unroll
            for (int mt = 0; mt < 4; mt++) {
                int rowA = mt * 16 + (lane & 15);
                uint32_t off = rowA * 128 + (((ks * 2 + (lane >> 4)) ^ (rowA & 7)) << 4);
                LDMX4(ah[mt], aAh + off);
                LDMX4(al[mt], aAl + off);
            }
            uint32_t bh[2][2], bl[2][2];
#pragma unroll
            for (int j = 0; j < 2; j++) {
                int krow = ks * 16 + (lane & 15);
                uint32_t off = krow * 128 + (((w * 2 + j) ^ (krow & 7)) << 4);
                asm volatile("ldmatrix.sync.aligned.m8n8.x2.trans.shared.b16 {%0,%1}, [%2];"
                    : "=r"(bh[j][0]), "=r"(bh[j][1]) : "r"(aBh + off));
                asm volatile("ldmatrix.sync.aligned.m8n8.x2.trans.shared.b16 {%0,%1}, [%2];"
                    : "=r"(bl[j][0]), "=r"(bl[j][1]) : "r"(aBl + off));
            }
#pragma unroll
            for (int mt = 0; mt < 4; mt++)
#pragma unroll
                for (int j = 0; j < 2; j++) {
                    MMA_BF16(c[mt][j], ah[mt], bh[j]);
                    MMA_BF16(c[mt][j], ah[mt], bl[j]);
                    MMA_BF16(c[mt][j], al[mt], bh[j]);
                }
        }
    }

    const int g = lane >> 2, cc = (lane & 3) * 2;
#pragma unroll
    for (int mt = 0; mt < 4; mt++)
#pragma unroll
        for (int j = 0; j < 2; j++) {
            int row = mt * 16 + g;
            int col = w * 16 + j * 8 + cc;
            size_t o = (size_t)(b * 64 + row) * 512 + h * 64 + col;
            uint32_t hh, ll;
            bsplit2(c[mt][j][0], c[mt][j][1], hh, ll);
            *(uint32_t*)(g_cb_hi + o) = hh;
            *(uint32_t*)(g_cb_lo + o) = ll;
            bsplit2(c[mt][j][2], c[mt][j][3], hh, ll);
            o += (size_t)8 * 512;
            *(uint32_t*)(g_cb_hi + o) = hh;
            *(uint32_t*)(g_cb_lo + o) = ll;
        }
}

// ================= final (128x64 tiles) =================
__global__ void __launch_bounds__(256) final_mma_kernel(float* __restrict__ out)
{
    const int m0 = blockIdx.y * 128, n0 = blockIdx.x * 64;
    mma_gemm128(g_cb_hi, g_cb_lo, m0,
                g_wt_hi + 3 * 262144, g_wt_lo + 3 * 262144, n0,
                out + (size_t)m0 * 512 + n0, nullptr, nullptr);
}

// ================= launch =================
extern "C" void kernel_launch(void* const* d_in, const int* in_sizes, int n_in,
                              void* d_out, int out_size)
{
    (void)in_sizes; (void)n_in; (void)out_size;
    const float* pe = (const float*)d_in[0];
    const float* rf = (const float*)d_in[1];
    const float* Wq = (const float*)d_in[3];
    const float* Wk = (const float*)d_in[4];
    const float* Wv = (const float*)d_in[5];
    const float* Wo = (const float*)d_in[6];
    float* out = (float*)d_out;

    prep_kernel        <<<1664, 256>>>(pe, Wq, Wk, Wv, Wo);
    proj_mma_kernel    <<<dim3(8, 8, 3), 256>>>();
    qs_kernel          <<<384, 128>>>();
    attn_mma_kernel    <<<1024, 256>>>(rf);
    outmerge_mma_kernel<<<128, 128>>>();
    final_mma_kernel   <<<dim3(8, 8), 256>>>(out);
}

// round 17
// speedup vs baseline: 1.1451x; 1.1451x over previous
#include <cuda_runtime.h>
#include <cuda_bf16.h>
#include <cstdint>
#include <math.h>

#define PB 16
#define PP 64
#define PF 128
#define PH 8
#define PDM 512
#define PBP 1024

typedef unsigned long long u64;

// ================= helpers =================
__device__ __forceinline__ uint32_t smem_to_u32(const void* p) {
    uint32_t a;
    asm("{ .reg .u64 t; cvta.to.shared.u64 t, %1; cvt.u32.u64 %0, t; }" : "=r"(a) : "l"(p));
    return a;
}

#define SW128(o) ((o) ^ (((o) >> 3) & 0x70))

#define LDMX4(r, a) \
    asm volatile("ldmatrix.sync.aligned.m8n8.x4.shared.b16 {%0,%1,%2,%3}, [%4];" \
        : "=r"((r)[0]), "=r"((r)[1]), "=r"((r)[2]), "=r"((r)[3]) : "r"(a))

#define LDMX4T(r, a) \
    asm volatile("ldmatrix.sync.aligned.m8n8.x4.trans.shared.b16 {%0,%1,%2,%3}, [%4];" \
        : "=r"((r)[0]), "=r"((r)[1]), "=r"((r)[2]), "=r"((r)[3]) : "r"(a))

#define MMA_BF16(c, a, b) \
    asm volatile("mma.sync.aligned.m16n8k16.row.col.f32.bf16.bf16.f32 " \
        "{%0,%1,%2,%3}, {%4,%5,%6,%7}, {%8,%9}, {%0,%1,%2,%3};" \
        : "+f"((c)[0]), "+f"((c)[1]), "+f"((c)[2]), "+f"((c)[3]) \
        : "r"((a)[0]), "r"((a)[1]), "r"((a)[2]), "r"((a)[3]), "r"((b)[0]), "r"((b)[1]))

// ================= scratch =================
__device__ float g_sb[PB * PH * PP * PP];
__device__ __nv_bfloat16 g_pe_hi[PBP * PDM], g_pe_lo[PBP * PDM];
__device__ __nv_bfloat16 g_qh[PBP * PDM],   g_ql[PBP * PDM];
__device__ __nv_bfloat16 g_kbh[PBP * PDM],  g_kbl[PBP * PDM];
__device__ __nv_bfloat16 g_vbh[PBP * PDM],  g_vbl[PBP * PDM];
__device__ __nv_bfloat16 g_qkh[PBP * PH * PF], g_qkl[PBP * PH * PF];
__device__ __nv_bfloat16 g_ath[PB * PH * PP * PP], g_atl[PB * PH * PP * PP];
__device__ __nv_bfloat16 g_arh[PBP * PH * PF], g_arl[PBP * PH * PF];
__device__ __nv_bfloat16 g_cb_hi[PBP * PDM], g_cb_lo[PBP * PDM];
__device__ __nv_bfloat16 g_wt_hi[4 * 512 * 512], g_wt_lo[4 * 512 * 512];
__device__ __nv_bfloat16 g_wkf_hi[PF * PDM], g_wkf_lo[PF * PDM];
__device__ __nv_bfloat16 g_wvfh[PF * PDM],  g_wvfl[PF * PDM];

__device__ __forceinline__ void bsplit(float x, __nv_bfloat16& h, __nv_bfloat16& l)
{
    h = __float2bfloat16_rn(x);
    l = __float2bfloat16_rn(x - __bfloat162float(h));
}
__device__ __forceinline__ void bsplit2(float a, float b, uint32_t& h2, uint32_t& l2)
{
    asm("cvt.rn.bf16x2.f32 %0, %1, %2;" : "=r"(h2) : "f"(b), "f"(a));
    float af = __uint_as_float(h2 << 16);
    float bf = __uint_as_float(h2 & 0xFFFF0000u);
    float ar = a - af, br = b - bf;
    asm("cvt.rn.bf16x2.f32 %0, %1, %2;" : "=r"(l2) : "f"(br), "f"(ar));
}

// ================= prep: pe split | W transpose+split | Wkf/Wvf split =================
__global__ void __launch_bounds__(256) prep_kernel(const float* __restrict__ pe,
                                                   const float* __restrict__ Wq,
                                                   const float* __restrict__ Wk,
                                                   const float* __restrict__ Wv,
                                                   const float* __restrict__ Wo)
{
    const int bx = blockIdx.x, tid = threadIdx.x;

    if (bx < 512) {
        int idx = bx * 256 + tid;
        float4 v = *(const float4*)(pe + (size_t)idx * 4);
        uint2 h2, l2;
        bsplit2(v.x, v.y, h2.x, l2.x);
        bsplit2(v.z, v.w, h2.y, l2.y);
        *(uint2*)(g_pe_hi + (size_t)idx * 4) = h2;
        *(uint2*)(g_pe_lo + (size_t)idx * 4) = l2;
    } else if (bx < 1536) {
        __shared__ float tile[32 * 33];
        const int wb = bx - 512;
        const int z = wb >> 8, rem = wb & 255;
        const int n0 = (rem & 15) * 32, k0 = (rem >> 4) * 32;
        const float* W = (z == 0) ? Wq : (z == 1) ? Wk : (z == 2) ? Wv : Wo;
        const int tx = tid & 31, ty = tid >> 5;
#pragma unroll
        for (int j = 0; j < 4; j++)
            tile[(ty + j * 8) * 33 + tx] = W[(size_t)(k0 + ty + j * 8) * 512 + n0 + tx];
        __syncthreads();
#pragma unroll
        for (int j = 0; j < 4; j++) {
            float v = tile[tx * 33 + ty + j * 8];
            __nv_bfloat16 h, l; bsplit(v, h, l);
            size_t o = (size_t)z * 262144 + (size_t)(n0 + ty + j * 8) * 512 + k0 + tx;
            g_wt_hi[o] = h; g_wt_lo[o] = l;
        }
    } else {
        const int which = (bx - 1536) >> 6;
        const int idx = ((bx - 1536) & 63) * 256 + tid;
        const float* src = (which == 0) ? Wk : Wv;
        float4 v = *(const float4*)(src + (size_t)512 * 512 + (size_t)idx * 4);
        uint2 h2, l2;
        bsplit2(v.x, v.y, h2.x, l2.x);
        bsplit2(v.z, v.w, h2.y, l2.y);
        __nv_bfloat16* dh = (which == 0) ? g_wkf_hi : g_wvfh;
        __nv_bfloat16* dl = (which == 0) ? g_wkf_lo : g_wvfl;
        *(uint2*)(dh + (size_t)idx * 4) = h2;
        *(uint2*)(dl + (size_t)idx * 4) = l2;
    }
}

// ================= 64x64 warp-MMA tile (128 threads), register-prefetch pipelined =================
__device__ __forceinline__ void mma_gemm(const __nv_bfloat16* __restrict__ Ahi,
                                         const __nv_bfloat16* __restrict__ Alo,
                                         int m0, int koffA,
                                         const __nv_bfloat16* __restrict__ Bhi,
                                         const __nv_bfloat16* __restrict__ Blo,
                                         int n0, int koffB, int nch,
                                         float* Cf, __nv_bfloat16* Ch, __nv_bfloat16* Cl, int ldc)
{
    __shared__ __nv_bfloat16 sAh[4096], sAl[4096], sBh[4096], sBl[4096];
    const int tid = threadIdx.x, lane = tid & 31, wid = tid >> 5;
    const int wm = (wid & 1) * 32, wn = (wid >> 1) * 32;
    const int lr = tid >> 1, lh = tid & 1;

    const uint32_t bAh = smem_to_u32(sAh), bAl = smem_to_u32(sAl);
    const uint32_t bBh = smem_to_u32(sBh), bBl = smem_to_u32(sBl);

    const uint32_t rowA = wm + (lane & 15);
    const uint32_t kbA  = (lane >> 4) * 16;
    const uint32_t rowB = wn + (lane & 7) + ((lane >> 4) << 3);
    const uint32_t kbB  = ((lane >> 3) & 1) * 16;

    uint4 pAh[4], pAl[4], pBh[4], pBl[4];

    auto load_chunk = [&](int ch) {
        const size_t aoff = (size_t)(m0 + lr) * 512 + koffA + ch * 64 + lh * 32;
        const size_t boff = (size_t)(n0 + lr) * 512 + koffB + ch * 64 + lh * 32;
#pragma unroll
        for (int j = 0; j < 4; j++) {
            pAh[j] = ((const uint4*)(Ahi + aoff))[j];
            pAl[j] = ((const uint4*)(Alo + aoff))[j];
            pBh[j] = ((const uint4*)(Bhi + boff))[j];
            pBl[j] = ((const uint4*)(Blo + boff))[j];
        }
    };
    auto store_chunk = [&]() {
#pragma unroll
        for (int j = 0; j < 4; j++) {
            uint32_t o = SW128((uint32_t)(lr * 128 + lh * 64 + j * 16));
            *(uint4*)((char*)sAh + o) = pAh[j];
            *(uint4*)((char*)sAl + o) = pAl[j];
            *(uint4*)((char*)sBh + o) = pBh[j];
            *(uint4*)((char*)sBl + o) = pBl[j];
        }
    };

    float c[2][4][4] = {};

    load_chunk(0);
    store_chunk();
    __syncthreads();

    for (int ch = 0; ch < nch; ch++) {
        if (ch + 1 < nch) load_chunk(ch + 1);

#pragma unroll
        for (int ks = 0; ks < 4; ks++) {
            const uint32_t kA = ks * 32 + kbA;
            const uint32_t kB = ks * 32 + kbB;
            const uint32_t oA0 = SW128(rowA * 128 + kA);
            const uint32_t oA1 = SW128((rowA + 16) * 128 + kA);
            const uint32_t oB0 = SW128(rowB * 128 + kB);
            const uint32_t oB1 = SW128((rowB + 16) * 128 + kB);

            uint32_t ah0[4], ah1[4], al0[4], al1[4];
            LDMX4(ah0, bAh + oA0); LDMX4(ah1, bAh + oA1);
            LDMX4(al0, bAl + oA0); LDMX4(al1, bAl + oA1);
            uint32_t bh0[4], bh1[4], bl0[4], bl1[4];
            LDMX4(bh0, bBh + oB0); LDMX4(bh1, bBh + oB1);
            LDMX4(bl0, bBl + oB0); LDMX4(bl1, bBl + oB1);

            uint32_t* Ah[2] = { ah0, ah1 };
            uint32_t* Al[2] = { al0, al1 };
            uint32_t* Bh[4] = { bh0, bh0 + 2, bh1, bh1 + 2 };
            uint32_t* Bl[4] = { bl0, bl0 + 2, bl1, bl1 + 2 };
#pragma unroll
            for (int mt = 0; mt < 2; mt++) {
#pragma unroll
                for (int j = 0; j < 4; j++) {
                    MMA_BF16(c[mt][j], Ah[mt], Bh[j]);
                    MMA_BF16(c[mt][j], Ah[mt], Bl[j]);
                    MMA_BF16(c[mt][j], Al[mt], Bh[j]);
                }
            }
        }
        if (ch + 1 < nch) {
            __syncthreads();
            store_chunk();
            __syncthreads();
        }
    }

    const int g = lane >> 2, cc = (lane & 3) * 2;
#pragma unroll
    for (int mt = 0; mt < 2; mt++)
#pragma unroll
        for (int j = 0; j < 4; j++) {
            int row = wm + mt * 16 + g;
            int col = wn + j * 8 + cc;
            if (Cf) {
                *(float2*)(Cf + (size_t)row * ldc + col) = make_float2(c[mt][j][0], c[mt][j][1]);
                *(float2*)(Cf + (size_t)(row + 8) * ldc + col) = make_float2(c[mt][j][2], c[mt][j][3]);
            }
            if (Ch) {
                uint32_t h2, l2;
                bsplit2(c[mt][j][0], c[mt][j][1], h2, l2);
                *(uint32_t*)(Ch + (size_t)row * ldc + col) = h2;
                *(uint32_t*)(Cl + (size_t)row * ldc + col) = l2;
                bsplit2(c[mt][j][2], c[mt][j][3], h2, l2);
                *(uint32_t*)(Ch + (size_t)(row + 8) * ldc + col) = h2;
                *(uint32_t*)(Cl + (size_t)(row + 8) * ldc + col) = l2;
            }
        }
}

// ================= proj: q, k_base, v_base bf16 hi/lo (64x64 tiles) =================
__global__ void __launch_bounds__(128) proj_mma_kernel()
{
    const int z = blockIdx.z;
    const int m0 = blockIdx.y * 64, n0 = blockIdx.x * 64;
    const size_t coff = (size_t)m0 * 512 + n0;
    __nv_bfloat16 *Ch, *Cl;
    if (z == 0)      { Ch = g_qh + coff;  Cl = g_ql + coff; }
    else if (z == 1) { Ch = g_kbh + coff; Cl = g_kbl + coff; }
    else             { Ch = g_vbh + coff; Cl = g_vbl + coff; }
    mma_gemm(g_pe_hi, g_pe_lo, m0, 0,
             g_wt_hi + (size_t)z * 262144, g_wt_lo + (size_t)z * 262144, n0, 0, 8,
             nullptr, Ch, Cl, 512);
}

// ================= qs (64x64 path) =================
__global__ void __launch_bounds__(128) qs_kernel()
{
    if (blockIdx.x < 256) {
        const int h = blockIdx.x >> 5, r = blockIdx.x & 31;
        const int mt = r >> 1, nt = r & 1;
        const int m0 = mt * 64, n0 = nt * 64;
        const size_t coff = (size_t)m0 * 1024 + h * 128 + n0;
        mma_gemm(g_qh, g_ql, m0, h * 64,
                 g_wkf_hi, g_wkf_lo, n0, h * 64, 1,
                 nullptr, g_qkh + coff, g_qkl + coff, 1024);
    } else {
        const int sb = blockIdx.x - 256;
        const int b = sb >> 3, h = sb & 7;
        mma_gemm(g_qh, g_ql, b * 64, h * 64,
                 g_kbh, g_kbl, b * 64, h * 64, 1,
                 g_sb + (size_t)(b * 8 + h) * 4096, nullptr, nullptr, 64);
    }
}

// ================= attn: coalesced rf load; scores C=[p x h]; ar via x4.trans =================
__global__ void __launch_bounds__(256, 3) attn_mma_kernel(const float* __restrict__ rf)
{
    __shared__ __nv_bfloat16 rf_h[64 * 128], rf_l[64 * 128];
    __shared__ __nv_bfloat16 qk_h[8 * 128],  qk_l[8 * 128];
    __shared__ __nv_bfloat16 at_h[8 * 64],   at_l[8 * 64];
    __shared__ float s_s[8 * 68];

    const int bq = blockIdx.x;
    const int b = bq >> 6, q = bq & 63;
    const int tid = threadIdx.x, lane = tid & 31, w = tid >> 5;

    // ---- load + split rf: LINEAR coalesced ----
    {
        const float4* rfg = (const float4*)(rf + (size_t)bq * 8192);
        float4 raw[8];
#pragma unroll
        for (int j = 0; j < 8; j++) raw[j] = rfg[j * 256 + tid];
#pragma unroll
        for (int j = 0; j < 8; j++) {
            int pidx = j * 256 + tid;
            uint32_t h0, l0, h1, l1;
            bsplit2(raw[j].x, raw[j].y, h0, l0);
            bsplit2(raw[j].z, raw[j].w, h1, l1);
            int p = pidx >> 5, q4 = pidx & 31;
            uint32_t off = p * 256 + ((((uint32_t)q4 >> 1) ^ (p & 7)) << 4) + (q4 & 1) * 8;
            *(uint2*)((char*)rf_h + off) = make_uint2(h0, h1);
            *(uint2*)((char*)rf_l + off) = make_uint2(l0, l1);
        }
    }
    // ---- load qk (bf16 hi/lo, threads 0-127) ----
    if (tid < 128) {
        const int h = tid >> 4, c = tid & 15;
        const size_t o = (size_t)bq * 1024 + h * 128 + c * 8;
        uint4 hv = *(const uint4*)(g_qkh + o);
        uint4 lv = *(const uint4*)(g_qkl + o);
        int cs = c ^ h;
        *(uint4*)((char*)qk_h + h * 256 + cs * 16) = hv;
        *(uint4*)((char*)qk_l + h * 256 + cs * 16) = lv;
    }
    __syncthreads();

    const uint32_t bRfh = smem_to_u32(rf_h), bRfl = smem_to_u32(rf_l);

    // ---- scores_rel: warps 0-3, C = [16 p x 8 h], A = rf, B = qk ----
    if (w < 4) {
        const uint32_t bQh = smem_to_u32(qk_h), bQl = smem_to_u32(qk_l);
        const uint32_t prow = w * 16 + (lane & 15);
        const uint32_t akb = lane >> 4;
        const uint32_t brow = lane & 7;
        const uint32_t bcq = lane >> 3;

        float c0[4] = {};
#pragma unroll
        for (int ks32 = 0; ks32 < 4; ks32++) {
            uint32_t bh[4], bl[4];
            {
                uint32_t bc = ks32 * 4 + bcq;
                uint32_t boff = brow * 256 + ((bc ^ brow) << 4);
                LDMX4(bh, bQh + boff);
                LDMX4(bl, bQl + boff);
            }
#pragma unroll
            for (int half = 0; half < 2; half++) {
                uint32_t ac = (ks32 * 2 + half) * 2 + akb;
                uint32_t aoff = prow * 256 + ((ac ^ (prow & 7)) << 4);
                uint32_t ah[4], al[4];
                LDMX4(ah, bRfh + aoff);
                LDMX4(al, bRfl + aoff);
                MMA_BF16(c0, ah, bh + half * 2);
                MMA_BF16(c0, ah, bl + half * 2);
                MMA_BF16(c0, al, bh + half * 2);
            }
        }
        const int g = lane >> 2, hc = (lane & 3) * 2;
        const int p0 = w * 16 + g;
#pragma unroll
        for (int j = 0; j < 2; j++) {
            int h = hc + j;
            const float* sbr = g_sb + ((size_t)(b * 8 + h) * 64 + q) * 64;
            s_s[h * 68 + p0]     = 0.125f * (c0[j]     + sbr[p0]);
            s_s[h * 68 + p0 + 8] = 0.125f * (c0[2 + j] + sbr[p0 + 8]);
        }
    }
    __syncthreads();

    // ---- softmax: warp w -> head w ----
    {
        const int h = w, l = lane;
        float a0 = s_s[h * 68 + 2 * l], a1 = s_s[h * 68 + 2 * l + 1];
        float m = fmaxf(a0, a1);
#pragma unroll
        for (int off = 16; off; off >>= 1) m = fmaxf(m, __shfl_xor_sync(0xffffffffu, m, off));
        float e0 = __expf(a0 - m), e1 = __expf(a1 - m);
        float s = e0 + e1;
#pragma unroll
        for (int off = 16; off; off >>= 1) s += __shfl_xor_sync(0xffffffffu, s, off);
        float inv = 1.f / s;
        float p0 = e0 * inv, p1 = e1 * inv;
        uint32_t hh, ll;
        bsplit2(p0, p1, hh, ll);
        const size_t go = ((size_t)(b * 8 + h) * 64 + q) * 64 + 2 * l;
        *(uint32_t*)(g_ath + go) = hh;
        *(uint32_t*)(g_atl + go) = ll;
        uint32_t off8 = h * 128 + ((((uint32_t)l >> 2) ^ h) << 4) + (l & 3) * 4;
        *(uint32_t*)((char*)at_h + off8) = hh;
        *(uint32_t*)((char*)at_l + off8) = ll;
    }
    __syncthreads();

    // ---- ar: all 8 warps, warp w covers f [w*16, w*16+16); rf^T via x4.trans ----
    {
        const uint32_t bAth = smem_to_u32(at_h), bAtl = smem_to_u32(at_l);
        const int arow = lane & 7;
        const int akc = (lane >> 4) & 1;
        const int brow = lane & 15;
        const int f16i = w * 2 + (lane >> 4);

        float c[2][4] = {};
#pragma unroll
        for (int ks = 0; ks < 4; ks++) {
            uint32_t aoff = arow * 128 + (((ks * 2 + akc) ^ arow) << 4);
            uint32_t ah[4], al[4];
            LDMX4(ah, bAth + aoff); LDMX4(al, bAtl + aoff);
            const int p = ks * 16 + brow;
            uint32_t boff = p * 256 + ((f16i ^ (p & 7)) << 4);
            uint32_t bh[4], bl[4];
            LDMX4T(bh, bRfh + boff);
            LDMX4T(bl, bRfl + boff);
#pragma unroll
            for (int ft = 0; ft < 2; ft++) {
                MMA_BF16(c[ft], ah, bh + ft * 2);
                MMA_BF16(c[ft], ah, bl + ft * 2);
                MMA_BF16(c[ft], al, bh + ft * 2);
            }
        }
        const int h = lane >> 2, fc = (lane & 3) * 2;
        const size_t base = (size_t)bq * 1024 + h * 128 + w * 16;
#pragma unroll
        for (int ft = 0; ft < 2; ft++) {
            uint32_t hh, ll;
            bsplit2(c[ft][0], c[ft][1], hh, ll);
            *(uint32_t*)(g_arh + base + ft * 8 + fc) = hh;
            *(uint32_t*)(g_arl + base + ft * 8 + fc) = ll;
        }
    }
}

// ================= outmerge (tensor-core): cb = at@vb + ar@Wvf -> bf16 hi/lo =================
__global__ void __launch_bounds__(128) outmerge_mma_kernel()
{
    __shared__ __nv_bfloat16 sAh[4096], sAl[4096], sBh[4096], sBl[4096];
    const int bx = blockIdx.x;
    const int b = bx >> 3, h = bx & 7;
    const int tid = threadIdx.x, lane = tid & 31, w = tid >> 5;
    const int lr = tid >> 1, lh = tid & 1;

    const uint32_t aAh = smem_to_u32(sAh), aAl = smem_to_u32(sAl);
    const uint32_t aBh = smem_to_u32(sBh), aBl = smem_to_u32(sBl);

    float c[4][2][4] = {};

    for (int ch = 0; ch < 3; ch++) {
        const __nv_bfloat16 *Ah, *Al, *Bh, *Bl;
        size_t aoff, boff;
        if (ch == 0) {
            Ah = g_ath; Al = g_atl;
            aoff = ((size_t)(b * 8 + h) * 64 + lr) * 64 + lh * 32;
            Bh = g_vbh; Bl = g_vbl;
            boff = (size_t)(b * 64 + lr) * 512 + h * 64 + lh * 32;
        } else {
            const int fc = ch - 1;
            Ah = g_arh; Al = g_arl;
            aoff = (size_t)(b * 64 + lr) * 1024 + h * 128 + fc * 64 + lh * 32;
            Bh = g_wvfh; Bl = g_wvfl;
            boff = (size_t)(fc * 64 + lr) * 512 + h * 64 + lh * 32;
        }
        uint4 rAh[2], rAl[2], rBh[2], rBl[2];
        uint4 rAh2[2], rAl2[2], rBh2[2], rBl2[2];
#pragma unroll
        for (int j = 0; j < 2; j++) {
            rAh[j]  = ((const uint4*)(Ah + aoff))[j];
            rAl[j]  = ((const uint4*)(Al + aoff))[j];
            rBh[j]  = ((const uint4*)(Bh + boff))[j];
            rBl[j]  = ((const uint4*)(Bl + boff))[j];
            rAh2[j] = ((const uint4*)(Ah + aoff))[2 + j];
            rAl2[j] = ((const uint4*)(Al + aoff))[2 + j];
            rBh2[j] = ((const uint4*)(Bh + boff))[2 + j];
            rBl2[j] = ((const uint4*)(Bl + boff))[2 + j];
        }
        __syncthreads();
#pragma unroll
        for (int j = 0; j < 2; j++) {
            int c16a = (lh * 4 + j) ^ (lr & 7);
            int c16b = (lh * 4 + 2 + j) ^ (lr & 7);
            *(uint4*)((char*)sAh + lr * 128 + c16a * 16) = rAh[j];
            *(uint4*)((char*)sAl + lr * 128 + c16a * 16) = rAl[j];
            *(uint4*)((char*)sBh + lr * 128 + c16a * 16) = rBh[j];
            *(uint4*)((char*)sBl + lr * 128 + c16a * 16) = rBl[j];
            *(uint4*)((char*)sAh + lr * 128 + c16b * 16) = rAh2[j];
            *(uint4*)((char*)sAl + lr * 128 + c16b * 16) = rAl2[j];
            *(uint4*)((char*)sBh + lr * 128 + c16b * 16) = rBh2[j];
            *(uint4*)((char*)sBl + lr * 128 + c16b * 16) = rBl2[j];
        }
        __syncthreads();

#pragma unroll
        for (int ks = 0; ks < 4; ks++) {
            uint32_t ah[4][4], al[4][4];
#pragma unroll
            for (int mt = 0; mt < 4; mt++) {
                int rowA = mt * 16 + (lane & 15);
                uint32_t off = rowA * 128 + (((ks * 2 + (lane >> 4)) ^ (rowA & 7)) << 4);
                LDMX4(ah[mt], aAh + off);
                LDMX4(al[mt], aAl + off);
            }
            uint32_t bh[2][2], bl[2][2];
#pragma unroll
            for (int j = 0; j < 2; j++) {
                int krow = ks * 16 + (lane & 15);
                uint32_t off = krow * 128 + (((w * 2 + j) ^ (krow & 7)) << 4);
                asm volatile("ldmatrix.sync.aligned.m8n8.x2.trans.shared.b16 {%0,%1}, [%2];"
                    : "=r"(bh[j][0]), "=r"(bh[j][1]) : "r"(aBh + off));
                asm volatile("ldmatrix.sync.aligned.m8n8.x2.trans.shared.b16 {%0,%1}, [%2];"
                    : "=r"(bl[j][0]), "=r"(bl[j][1]) : "r"(aBl + off));
            }
#pragma unroll
            for (int mt = 0; mt < 4; mt++)
#pragma unroll
                for (int j = 0; j < 2; j++) {
                    MMA_BF16(c[mt][j], ah[mt], bh[j]);
                    MMA_BF16(c[mt][j], ah[mt], bl[j]);
                    MMA_BF16(c[mt][j], al[mt], bh[j]);
                }
        }
    }

    const int g = lane >> 2, cc = (lane & 3) * 2;
#pragma unroll
    for (int mt = 0; mt < 4; mt++)
#pragma unroll
        for (int j = 0; j < 2; j++) {
            int row = mt * 16 + g;
            int col = w * 16 + j * 8 + cc;
            size_t o = (size_t)(b * 64 + row) * 512 + h * 64 + col;
            uint32_t hh, ll;
            bsplit2(c[mt][j][0], c[mt][j][1], hh, ll);
            *(uint32_t*)(g_cb_hi + o) = hh;
            *(uint32_t*)(g_cb_lo + o) = ll;
            bsplit2(c[mt][j][2], c[mt][j][3], hh, ll);
            o += (size_t)8 * 512;
            *(uint32_t*)(g_cb_hi + o) = hh;
            *(uint32_t*)(g_cb_lo + o) = ll;
        }
}

// ================= final (64x64 tiles) =================
__global__ void __launch_bounds__(128) final_mma_kernel(float* __restrict__ out)
{
    const int m0 = blockIdx.y * 64, n0 = blockIdx.x * 64;
    mma_gemm(g_cb_hi, g_cb_lo, m0, 0,
             g_wt_hi + 3 * 262144, g_wt_lo + 3 * 262144, n0, 0, 8,
             out + (size_t)m0 * 512 + n0, nullptr, nullptr, 512);
}

// ================= launch =================
extern "C" void kernel_launch(void* const* d_in, const int* in_sizes, int n_in,
                              void* d_out, int out_size)
{
    (void)in_sizes; (void)n_in; (void)out_size;
    const float* pe = (const float*)d_in[0];
    const float* rf = (const float*)d_in[1];
    const float* Wq = (const float*)d_in[3];
    const float* Wk = (const float*)d_in[4];
    const float* Wv = (const float*)d_in[5];
    const float* Wo = (const float*)d_in[6];
    float* out = (float*)d_out;

    prep_kernel        <<<1664, 256>>>(pe, Wq, Wk, Wv, Wo);
    proj_mma_kernel    <<<dim3(8, 16, 3), 128>>>();
    qs_kernel          <<<384, 128>>>();
    attn_mma_kernel    <<<1024, 256>>>(rf);
    outmerge_mma_kernel<<<128, 128>>>();
    final_mma_kernel   <<<dim3(8, 16), 128>>>(out);
}